// round 17
// baseline (speedup 1.0000x reference)
#include <cuda_runtime.h>
#include <math.h>
#include <stdint.h>

// ---------------------------------------------------------------------------
// AttentionLayer: B=16, T=4096, D=1024, NH=16, HD=64, Tq=1.
// Folded formulation (K/V never materialized). 10 kernels.
// R14: k_scores on tf32 mma.sync (measurement-verified fragment layouts).
// R17: k_wsum on tf32 mma; ws pad 20 -> static smem 47104 B (< 48 KB).
// ---------------------------------------------------------------------------

#define B_   16
#define T_   4096
#define D_   1024
#define NH_  16
#define HD_  64
#define NC_  32
#define TCH_ 128

typedef unsigned long long u64;

// scratch (no cudaMalloc allowed)
__device__ __align__(16) float  g_qp [8*B_*D_];       // qproj K-split partials
__device__ __align__(16) float  g_qt [B_*D_*NH_];     // [b][d][h] (scaled)
__device__ __align__(16) float  g_sc [B_*NH_*T_];     // scores [bh][t]
__device__ __align__(16) float2 g_ms [B_*NH_];        // (max, 1/sumexp)
__device__ __align__(16) float  g_up [NC_*B_*NH_*D_]; // wsum chunk partials
__device__ __align__(16) float  g_u  [B_*NH_*D_];     // [b][h][d]
__device__ __align__(16) float  g_cp [8*B_*D_];       // ctx K-split partials
__device__ __align__(16) float  g_h4 [4*B_*4*D_];     // ffn1 K-split partials
__device__ __align__(16) float  g_o8 [8*B_*D_];       // ffn2 K-split partials

// ---- packed f32x2 helpers -------------------------------------------------
__device__ __forceinline__ void fma2(u64 &acc, u64 a, u64 b) {
    asm("fma.rn.f32x2 %0, %1, %2, %0;" : "+l"(acc) : "l"(a), "l"(b));
}
__device__ __forceinline__ u64 pack2(float v) {
    u64 r; asm("mov.b64 %0, {%1, %1};" : "=l"(r) : "f"(v)); return r;
}
__device__ __forceinline__ u64 pack2b(float a, float b) {
    u64 r; asm("mov.b64 %0, {%1, %2};" : "=l"(r) : "f"(a), "f"(b)); return r;
}
__device__ __forceinline__ float2 unpack2(u64 v) {
    float2 r; asm("mov.b64 {%0, %1}, %2;" : "=f"(r.x), "=f"(r.y) : "l"(v)); return r;
}
__device__ __forceinline__ float wred(float s) {
    #pragma unroll
    for (int o = 16; o > 0; o >>= 1) s += __shfl_xor_sync(0xffffffffu, s, o);
    return s;
}

// ---- tf32 mma helpers -----------------------------------------------------
__device__ __forceinline__ uint32_t f2tf(float x) {
    uint32_t r; asm("cvt.rna.tf32.f32 %0, %1;" : "=r"(r) : "f"(x)); return r;
}
__device__ __forceinline__ void mma_tf32(float* c, uint32_t a0, uint32_t a1,
                                         uint32_t a2, uint32_t a3,
                                         uint32_t b0, uint32_t b1) {
    asm volatile(
        "mma.sync.aligned.m16n8k8.row.col.f32.tf32.tf32.f32 "
        "{%0,%1,%2,%3}, {%4,%5,%6,%7}, {%8,%9}, {%0,%1,%2,%3};"
        : "+f"(c[0]), "+f"(c[1]), "+f"(c[2]), "+f"(c[3])
        : "r"(a0), "r"(a1), "r"(a2), "r"(a3), "r"(b0), "r"(b1));
}

// ===========================================================================
// GEMM64: 256 threads, 64-j tile x all 16 b over NCHUNK*32 k. Double-buffered.
// ===========================================================================
#define GEMM64(WL4, XL, NCHUNK, KOFF)                                          \
    int tid = threadIdx.x, jj = tid >> 3, bp = tid & 7;                        \
    __shared__ u64  Ws[2][64][34];                                             \
    __shared__ float Xs[2][32][18];                                            \
    u64 accA = 0ull, accB = 0ull;                                              \
    const int r0 = tid >> 3, c0 = (tid * 4) & 31;                              \
    const int r1 = 32 + r0,  c1 = c0;                                          \
    const int xk = tid & 31, xb = tid >> 5;                                    \
    float4 w0, w1; float x0, x1;                                               \
    w0 = WL4(r0, (KOFF) + c0); w1 = WL4(r1, (KOFF) + c1);                      \
    x0 = XL(xb, (KOFF) + xk);  x1 = XL(xb + 8, (KOFF) + xk);                   \
    {                                                                          \
        ulonglong2* p0 = (ulonglong2*)&Ws[0][r0][c0];                          \
        p0[0] = make_ulonglong2(pack2(w0.x), pack2(w0.y));                     \
        p0[1] = make_ulonglong2(pack2(w0.z), pack2(w0.w));                     \
        ulonglong2* p1 = (ulonglong2*)&Ws[0][r1][c1];                          \
        p1[0] = make_ulonglong2(pack2(w1.x), pack2(w1.y));                     \
        p1[1] = make_ulonglong2(pack2(w1.z), pack2(w1.w));                     \
        Xs[0][xk][xb] = x0; Xs[0][xk][xb + 8] = x1;                            \
    }                                                                          \
    __syncthreads();                                                           \
    for (int ch = 0; ch < (NCHUNK); ch++) {                                    \
        int cur = ch & 1;                                                      \
        if (ch + 1 < (NCHUNK)) {                                               \
            int kb = (KOFF) + (ch + 1) * 32;                                   \
            w0 = WL4(r0, kb + c0); w1 = WL4(r1, kb + c1);                      \
            x0 = XL(xb, kb + xk);  x1 = XL(xb + 8, kb + xk);                   \
        }                                                                      \
        _Pragma("unroll")                                                      \
        for (int k = 0; k < 32; k++) {                                         \
            u64 xv = *(const u64*)&Xs[cur][k][bp * 2];                         \
            fma2(accA, Ws[cur][jj][k],      xv);                               \
            fma2(accB, Ws[cur][32 + jj][k], xv);                               \
        }                                                                      \
        if (ch + 1 < (NCHUNK)) {                                               \
            int nxt = cur ^ 1;                                                 \
            ulonglong2* p0 = (ulonglong2*)&Ws[nxt][r0][c0];                    \
            p0[0] = make_ulonglong2(pack2(w0.x), pack2(w0.y));                 \
            p0[1] = make_ulonglong2(pack2(w0.z), pack2(w0.w));                 \
            ulonglong2* p1 = (ulonglong2*)&Ws[nxt][r1][c1];                    \
            p1[0] = make_ulonglong2(pack2(w1.x), pack2(w1.y));                 \
            p1[1] = make_ulonglong2(pack2(w1.z), pack2(w1.w));                 \
            Xs[nxt][xk][xb] = x0; Xs[nxt][xk][xb + 8] = x1;                    \
        }                                                                      \
        __syncthreads();                                                       \
    }                                                                          \
    float2 vA = unpack2(accA), vB = unpack2(accB);

// ---------------------------------------------------------------------------
// K1: qproj partials.  grid (16 jb, 8 ks), 256 thr
__global__ __launch_bounds__(256) void k_qproj(const float* __restrict__ dec_h,
                                               const float* __restrict__ Wq) {
    int j0 = blockIdx.x * 64, ks = blockIdx.y;
#define WL4(r, k) (*(const float4*)&Wq[(size_t)(j0 + (r)) * D_ + (k)])
#define XLD(b, k) dec_h[(size_t)(b) * D_ + (k)]
    GEMM64(WL4, XLD, 4, ks * 128)
#undef WL4
#undef XLD
    float* o = g_qp + (size_t)ks * (B_ * D_);
    o[(size_t)(2 * bp)     * D_ + j0 + jj]      = vA.x;
    o[(size_t)(2 * bp + 1) * D_ + j0 + jj]      = vA.y;
    o[(size_t)(2 * bp)     * D_ + j0 + 32 + jj] = vB.x;
    o[(size_t)(2 * bp + 1) * D_ + j0 + 32 + jj] = vB.y;
}

// ---------------------------------------------------------------------------
// K2: qt[b][d][h] = SCALE * Wk_h^T q_h (sums 8 qproj partials)
__global__ __launch_bounds__(128) void k_qtilde(const float* __restrict__ Wk) {
    int h = blockIdx.x >> 3, d0 = (blockIdx.x & 7) * 128, tid = threadIdx.x;
    __shared__ u64 qs2[64 * 8];          // [j][bpair]
    #pragma unroll
    for (int i = 0; i < 4; i++) {
        int idx = i * 128 + tid; int j = idx >> 3, bpp = idx & 7;
        float a = 0.f, bb = 0.f;
        #pragma unroll
        for (int ks = 0; ks < 8; ks++) {
            a  += g_qp[(size_t)ks * (B_ * D_) + (2 * bpp)     * D_ + h * HD_ + j];
            bb += g_qp[(size_t)ks * (B_ * D_) + (2 * bpp + 1) * D_ + h * HD_ + j];
        }
        qs2[j * 8 + bpp] = pack2b(a, bb);
    }
    __syncthreads();
    u64 acc[8];
    #pragma unroll
    for (int bp = 0; bp < 8; bp++) acc[bp] = 0ull;
    #pragma unroll 4
    for (int j = 0; j < HD_; j++) {
        u64 w2 = pack2(Wk[(size_t)(h * HD_ + j) * D_ + d0 + tid]);
        #pragma unroll
        for (int bp = 0; bp < 8; bp++) fma2(acc[bp], w2, qs2[j * 8 + bp]);
    }
    #pragma unroll
    for (int bp = 0; bp < 8; bp++) {
        float2 v = unpack2(acc[bp]);
        g_qt[(size_t)(2 * bp)     * D_ * NH_ + (d0 + tid) * NH_ + h] = 0.125f * v.x;
        g_qt[(size_t)(2 * bp + 1) * D_ * NH_ + (d0 + tid) * NH_ + h] = 0.125f * v.y;
    }
}

// ---------------------------------------------------------------------------
// K3: scores via tf32 mma (R14-proven).  grid (16 b, 32 t-tiles), 256 thr.
__global__ __launch_bounds__(256) void k_scores(const float* __restrict__ enc) {
    const int b = blockIdx.x, t0 = blockIdx.y * 128;
    const int tid = threadIdx.x, w = tid >> 5, lane = tid & 31;
    __shared__ uint32_t es[2][128][36];
    __shared__ uint32_t qs[2][16][36];
    const float* encb = enc + ((size_t)b * T_ + t0) * D_;
    const float* qtb  = g_qt + (size_t)b * D_ * NH_;

    float c0[4] = {0.f, 0.f, 0.f, 0.f};
    float c1[4] = {0.f, 0.f, 0.f, 0.f};

    float4 pe[4]; float pq[2];
    #pragma unroll
    for (int i = 0; i < 4; i++) {
        int idx = i * 256 + tid; int row = idx >> 3, c4 = idx & 7;
        pe[i] = *(const float4*)&encb[(size_t)row * D_ + c4 * 4];
    }
    #pragma unroll
    for (int i = 0; i < 2; i++) {
        int idx = i * 256 + tid; int h = idx & 15, k = idx >> 4;
        pq[i] = qtb[(size_t)k * NH_ + h];
    }
    #pragma unroll
    for (int i = 0; i < 4; i++) {
        int idx = i * 256 + tid; int row = idx >> 3, c4 = idx & 7;
        uint4 t4 = make_uint4(f2tf(pe[i].x), f2tf(pe[i].y),
                              f2tf(pe[i].z), f2tf(pe[i].w));
        *(uint4*)&es[0][row][c4 * 4] = t4;
    }
    #pragma unroll
    for (int i = 0; i < 2; i++) {
        int idx = i * 256 + tid; int h = idx & 15, k = idx >> 4;
        qs[0][h][k] = f2tf(pq[i]);
    }
    __syncthreads();

    const int arow = lane >> 2, acol = lane & 3;
    const int rbase = w * 16;

    for (int ch = 0; ch < 32; ch++) {
        int cur = ch & 1;
        if (ch + 1 < 32) {
            int k0 = (ch + 1) * 32;
            #pragma unroll
            for (int i = 0; i < 4; i++) {
                int idx = i * 256 + tid; int row = idx >> 3, c4 = idx & 7;
                pe[i] = *(const float4*)&encb[(size_t)row * D_ + k0 + c4 * 4];
            }
            #pragma unroll
            for (int i = 0; i < 2; i++) {
                int idx = i * 256 + tid; int h = idx & 15, k = idx >> 4;
                pq[i] = qtb[(size_t)(k0 + k) * NH_ + h];
            }
        }
        #pragma unroll
        for (int ks = 0; ks < 4; ks++) {
            int kk = ks * 8;
            uint32_t a0 = es[cur][rbase + arow    ][kk + acol];
            uint32_t a1 = es[cur][rbase + arow + 8][kk + acol];
            uint32_t a2 = es[cur][rbase + arow    ][kk + acol + 4];
            uint32_t a3 = es[cur][rbase + arow + 8][kk + acol + 4];
            uint32_t b0 = qs[cur][arow    ][kk + acol];
            uint32_t b1 = qs[cur][arow    ][kk + acol + 4];
            mma_tf32(c0, a0, a1, a2, a3, b0, b1);
            uint32_t b2 = qs[cur][8 + arow][kk + acol];
            uint32_t b3 = qs[cur][8 + arow][kk + acol + 4];
            mma_tf32(c1, a0, a1, a2, a3, b2, b3);
        }
        if (ch + 1 < 32) {
            int nxt = cur ^ 1;
            #pragma unroll
            for (int i = 0; i < 4; i++) {
                int idx = i * 256 + tid; int row = idx >> 3, c4 = idx & 7;
                uint4 t4 = make_uint4(f2tf(pe[i].x), f2tf(pe[i].y),
                                      f2tf(pe[i].z), f2tf(pe[i].w));
                *(uint4*)&es[nxt][row][c4 * 4] = t4;
            }
            #pragma unroll
            for (int i = 0; i < 2; i++) {
                int idx = i * 256 + tid; int h = idx & 15, k = idx >> 4;
                qs[nxt][h][k] = f2tf(pq[i]);
            }
        }
        __syncthreads();
    }

    int t = t0 + rbase + arow;
    int h0 = 2 * acol;
    g_sc[((size_t)b * NH_ + h0    ) * T_ + t]     = c0[0];
    g_sc[((size_t)b * NH_ + h0 + 1) * T_ + t]     = c0[1];
    g_sc[((size_t)b * NH_ + h0    ) * T_ + t + 8] = c0[2];
    g_sc[((size_t)b * NH_ + h0 + 1) * T_ + t + 8] = c0[3];
    int h1 = 8 + 2 * acol;
    g_sc[((size_t)b * NH_ + h1    ) * T_ + t]     = c1[0];
    g_sc[((size_t)b * NH_ + h1 + 1) * T_ + t]     = c1[1];
    g_sc[((size_t)b * NH_ + h1    ) * T_ + t + 8] = c1[2];
    g_sc[((size_t)b * NH_ + h1 + 1) * T_ + t + 8] = c1[3];
}

// ---------------------------------------------------------------------------
// K4: softmax STATS only: g_ms[bh] = (max, 1/sumexp).  grid 256, 256 thr.
__global__ __launch_bounds__(256) void k_stats() {
    int bh = blockIdx.x, tid = threadIdx.x;
    const float4* sc4 = (const float4*)(g_sc + (size_t)bh * T_);
    __shared__ float red[8];
    __shared__ float sbc;

    float4 v[4];
    float m = -1e30f;
    #pragma unroll
    for (int k = 0; k < 4; k++) {
        v[k] = sc4[(k << 8) + tid];
        m = fmaxf(m, fmaxf(fmaxf(v[k].x, v[k].y), fmaxf(v[k].z, v[k].w)));
    }
    #pragma unroll
    for (int o = 16; o > 0; o >>= 1) m = fmaxf(m, __shfl_xor_sync(0xffffffffu, m, o));
    if ((tid & 31) == 0) red[tid >> 5] = m;
    __syncthreads();
    if (tid == 0) {
        float mm = red[0];
        #pragma unroll
        for (int i = 1; i < 8; i++) mm = fmaxf(mm, red[i]);
        sbc = mm;
    }
    __syncthreads();
    m = sbc;
    float s = 0.f;
    #pragma unroll
    for (int k = 0; k < 4; k++) {
        s += (__expf(v[k].x - m) + __expf(v[k].y - m)) +
             (__expf(v[k].z - m) + __expf(v[k].w - m));
    }
    s = wred(s);
    __syncthreads();
    if ((tid & 31) == 0) red[tid >> 5] = s;
    __syncthreads();
    if (tid == 0) {
        float ss = 0.f;
        #pragma unroll
        for (int i = 0; i < 8; i++) ss += red[i];
        g_ms[bh] = make_float2(m, 1.f / ss);
    }
}

// ---------------------------------------------------------------------------
// K5: wsum via tf32 mma.  grid (16 b, 32 c), 128 thr (4 warps).
// M=16 (h), K=128 (t, smem-resident), N=1024 streamed in 32-col chunks.
// Static smem: ws 128*20*4=10240 + es 2*128*36*4=36864 -> 47104 B (< 48 KB).
__global__ __launch_bounds__(128) void k_wsum(const float* __restrict__ enc) {
    const int b = blockIdx.x, c = blockIdx.y;
    const int tid = threadIdx.x, w = tid >> 5, lane = tid & 31;
    __shared__ uint32_t ws[128][20];      // w (tf32 bits) [t][h]   10240 B
    __shared__ uint32_t es[2][128][36];   // enc (tf32 bits) [t][d] 36864 B
    const float* encb = enc + ((size_t)b * T_ + (size_t)c * TCH_) * D_;

    #pragma unroll
    for (int i = 0; i < 16; i++) {
        int idx = i * 128 + tid;
        int t = idx >> 4, h = idx & 15;
        float2 ms = g_ms[b * NH_ + h];
        float sc = g_sc[((size_t)b * NH_ + h) * T_ + c * TCH_ + t];
        ws[t][h] = f2tf(__expf(sc - ms.x) * ms.y);
    }
    float4 pe[8];
    #pragma unroll
    for (int i = 0; i < 8; i++) {
        int idx = i * 128 + tid;
        int row = idx >> 3, c4 = idx & 7;
        pe[i] = *(const float4*)&encb[(size_t)row * D_ + c4 * 4];
    }
    #pragma unroll
    for (int i = 0; i < 8; i++) {
        int idx = i * 128 + tid;
        int row = idx >> 3, c4 = idx & 7;
        *(uint4*)&es[0][row][c4 * 4] = make_uint4(f2tf(pe[i].x), f2tf(pe[i].y),
                                                  f2tf(pe[i].z), f2tf(pe[i].w));
    }
    __syncthreads();

    const int arow = lane >> 2, acol = lane & 3;
    uint32_t af[16][4];
    #pragma unroll
    for (int ks = 0; ks < 16; ks++) {
        int tk = ks * 8;
        af[ks][0] = ws[tk + acol    ][arow];
        af[ks][1] = ws[tk + acol    ][arow + 8];
        af[ks][2] = ws[tk + acol + 4][arow];
        af[ks][3] = ws[tk + acol + 4][arow + 8];
    }

    float* up = g_up + (((size_t)c * B_ + b) * NH_) * D_;
    const int dn = w * 8;

    for (int dc = 0; dc < 32; dc++) {
        int cur = dc & 1;
        if (dc + 1 < 32) {
            int d0 = (dc + 1) * 32;
            #pragma unroll
            for (int i = 0; i < 8; i++) {
                int idx = i * 128 + tid;
                int row = idx >> 3, c4 = idx & 7;
                pe[i] = *(const float4*)&encb[(size_t)row * D_ + d0 + c4 * 4];
            }
        }
        float cc[4] = {0.f, 0.f, 0.f, 0.f};
        #pragma unroll
        for (int ks = 0; ks < 16; ks++) {
            int tk = ks * 8;
            uint32_t b0 = es[cur][tk + acol    ][dn + arow];
            uint32_t b1 = es[cur][tk + acol + 4][dn + arow];
            mma_tf32(cc, af[ks][0], af[ks][1], af[ks][2], af[ks][3], b0, b1);
        }
        int dd = dc * 32 + dn + 2 * acol;
        *(float2*)&up[(size_t)(arow    ) * D_ + dd] = make_float2(cc[0], cc[1]);
        *(float2*)&up[(size_t)(arow + 8) * D_ + dd] = make_float2(cc[2], cc[3]);
        if (dc + 1 < 32) {
            int nxt = cur ^ 1;
            #pragma unroll
            for (int i = 0; i < 8; i++) {
                int idx = i * 128 + tid;
                int row = idx >> 3, c4 = idx & 7;
                *(uint4*)&es[nxt][row][c4 * 4] =
                    make_uint4(f2tf(pe[i].x), f2tf(pe[i].y),
                               f2tf(pe[i].z), f2tf(pe[i].w));
            }
        }
        __syncthreads();
    }
}

// ---------------------------------------------------------------------------
// K6: u = sum_c u_part   (wide streaming reduction, 1024 CTAs)
__global__ __launch_bounds__(256) void k_combine() {
    int idx = blockIdx.x * 256 + threadIdx.x;
    float s = 0.f;
    #pragma unroll
    for (int c = 0; c < NC_; c++) s += g_up[(size_t)c * (B_ * NH_ * D_) + idx];
    g_u[idx] = s;
}

// ---------------------------------------------------------------------------
// K7: ctx partials = Wv . u     grid (16 jb, 8 ks)
__global__ __launch_bounds__(256) void k_ctx(const float* __restrict__ Wv) {
    int j0 = blockIdx.x * 64, ks = blockIdx.y;
    int h  = blockIdx.x;
#define WL4(r, k) (*(const float4*)&Wv[(size_t)(j0 + (r)) * D_ + (k)])
#define XLD(b, k) g_u[((size_t)(b) * NH_ + h) * D_ + (k)]
    GEMM64(WL4, XLD, 4, ks * 128)
#undef WL4
#undef XLD
    float* o = g_cp + (size_t)ks * (B_ * D_);
    o[(size_t)(2 * bp)     * D_ + j0 + jj]      = vA.x;
    o[(size_t)(2 * bp + 1) * D_ + j0 + jj]      = vA.y;
    o[(size_t)(2 * bp)     * D_ + j0 + 32 + jj] = vB.x;
    o[(size_t)(2 * bp + 1) * D_ + j0 + 32 + jj] = vB.y;
}

// ---------------------------------------------------------------------------
// K8: ffn1 partials = cat(dec_h, sum_8 ctx_p) @ W1^T   grid (64 jb, 4 ks)
__global__ __launch_bounds__(256) void k_ffn1(const float* __restrict__ dec_h,
                                              const float* __restrict__ W1) {
    int j0 = blockIdx.x * 64, ks = blockIdx.y;
#define WL4(r, k) (*(const float4*)&W1[(size_t)(j0 + (r)) * (2 * D_) + (k)])
#define XLD(b, k) ((k) < D_ ? dec_h[(size_t)(b) * D_ + (k)]                    \
    : (((g_cp[(size_t)(b) * D_ + (k) - D_] +                                   \
         g_cp[(size_t)(B_ * D_) + (b) * D_ + (k) - D_]) +                      \
        (g_cp[(size_t)(2 * B_ * D_) + (b) * D_ + (k) - D_] +                   \
         g_cp[(size_t)(3 * B_ * D_) + (b) * D_ + (k) - D_])) +                 \
       ((g_cp[(size_t)(4 * B_ * D_) + (b) * D_ + (k) - D_] +                   \
         g_cp[(size_t)(5 * B_ * D_) + (b) * D_ + (k) - D_]) +                  \
        (g_cp[(size_t)(6 * B_ * D_) + (b) * D_ + (k) - D_] +                   \
         g_cp[(size_t)(7 * B_ * D_) + (b) * D_ + (k) - D_]))))
    GEMM64(WL4, XLD, 16, ks * 512)
#undef WL4
#undef XLD
    float* o = g_h4 + (size_t)ks * (B_ * 4 * D_);
    o[(size_t)(2 * bp)     * (4 * D_) + j0 + jj]      = vA.x;
    o[(size_t)(2 * bp + 1) * (4 * D_) + j0 + jj]      = vA.y;
    o[(size_t)(2 * bp)     * (4 * D_) + j0 + 32 + jj] = vB.x;
    o[(size_t)(2 * bp + 1) * (4 * D_) + j0 + 32 + jj] = vB.y;
}

// ---------------------------------------------------------------------------
// K9: ffn2 partials = silu(sum_4 h_p) @ W2^T   grid (16 jb, 8 ks)
__global__ __launch_bounds__(256) void k_ffn2(const float* __restrict__ W2) {
    int j0 = blockIdx.x * 64, ks = blockIdx.y;
#define WL4(r, k) (*(const float4*)&W2[(size_t)(j0 + (r)) * (4 * D_) + (k)])
#define XLD(b, k) ({                                                           \
        float _x = (g_h4[(size_t)(b) * (4 * D_) + (k)] +                       \
                    g_h4[(size_t)(B_ * 4 * D_) + (b) * (4 * D_) + (k)]) +      \
                   (g_h4[(size_t)(2 * B_ * 4 * D_) + (b) * (4 * D_) + (k)] +   \
                    g_h4[(size_t)(3 * B_ * 4 * D_) + (b) * (4 * D_) + (k)]);   \
        _x / (1.f + __expf(-_x)); })
    GEMM64(WL4, XLD, 16, ks * 512)
#undef WL4
#undef XLD
    float* o = g_o8 + (size_t)ks * (B_ * D_);
    o[(size_t)(2 * bp)     * D_ + j0 + jj]      = vA.x;
    o[(size_t)(2 * bp + 1) * D_ + j0 + jj]      = vA.y;
    o[(size_t)(2 * bp)     * D_ + j0 + 32 + jj] = vB.x;
    o[(size_t)(2 * bp + 1) * D_ + j0 + 32 + jj] = vB.y;
}

// ---------------------------------------------------------------------------
// K10: out = sum of 8 ffn2 partials   grid 16, 256 thr, float4
__global__ __launch_bounds__(256) void k_fin(float* __restrict__ outp) {
    int i = (blockIdx.x * 256 + threadIdx.x) * 4;
    float4 s = *(const float4*)&g_o8[i];
    #pragma unroll
    for (int ks = 1; ks < 8; ks++) {
        float4 p = *(const float4*)&g_o8[(size_t)ks * (B_ * D_) + i];
        s.x += p.x; s.y += p.y; s.z += p.z; s.w += p.w;
    }
    *(float4*)&outp[i] = s;
}

// ---------------------------------------------------------------------------
extern "C" void kernel_launch(void* const* d_in, const int* in_sizes, int n_in,
                              void* d_out, int out_size) {
    const float* dec_h = (const float*)d_in[0];
    const float* enc   = (const float*)d_in[1];
    const float* Wq    = (const float*)d_in[2];
    const float* Wk    = (const float*)d_in[3];
    const float* Wv    = (const float*)d_in[4];
    const float* W1    = (const float*)d_in[5];
    const float* W2    = (const float*)d_in[6];
    float* outp = (float*)d_out;

    k_qproj  <<<dim3(16, 8), 256>>>(dec_h, Wq);
    k_qtilde <<<128, 128>>>(Wk);
    k_scores <<<dim3(16, 32), 256>>>(enc);
    k_stats  <<<256, 256>>>();
    k_wsum   <<<dim3(16, 32), 128>>>(enc);
    k_combine<<<1024, 256>>>();
    k_ctx    <<<dim3(16, 8), 256>>>(Wv);
    k_ffn1   <<<dim3(64, 4), 256>>>(dec_h, W1);
    k_ffn2   <<<dim3(16, 8), 256>>>(W2);
    k_fin    <<<16, 256>>>(outp);
}